// round 1
// baseline (speedup 1.0000x reference)
#include <cuda_runtime.h>

static constexpr int H = 128, W = 128, Dz = 128;
static constexpr int HWD = H * W * Dz;

__global__ __launch_bounds__(256)
void warp_dti_kernel(const float* __restrict__ dti,
                     const float* __restrict__ ddf,
                     float* __restrict__ out)
{
    int idx = blockIdx.x * 256 + threadIdx.x;
    if (idx >= HWD) return;
    int z = idx & (Dz - 1);
    int y = (idx >> 7) & (W - 1);
    int x = idx >> 14;

    const float* __restrict__ d0 = ddf;
    const float* __restrict__ d1 = ddf + HWD;
    const float* __restrict__ d2 = ddf + 2 * HWD;

    float u0 = __ldg(d0 + idx), u1 = __ldg(d1 + idx), u2 = __ldg(d2 + idx);

    // ---- Jacobian via jnp.gradient semantics (central interior, one-sided edges) ----
    int xp = min(x + 1, H - 1), xm = max(x - 1, 0);
    int yp = min(y + 1, W - 1), ym = max(y - 1, 0);
    int zp = min(z + 1, Dz - 1), zm = max(z - 1, 0);
    float sx = 1.0f / (float)(xp - xm);
    float sy = 1.0f / (float)(yp - ym);
    float sz = 1.0f / (float)(zp - zm);

    int byz = y * Dz + z;
    int ixp = xp * (W * Dz) + byz, ixm = xm * (W * Dz) + byz;
    int row = x * (W * Dz);
    int iyp = row + yp * Dz + z, iym = row + ym * Dz + z;
    int izp = idx + (zp - z), izm = idx - (z - zm);

    // J[i][j] = d ddf_i / d axis_j + delta_ij
    float X00 = (__ldg(d0 + ixp) - __ldg(d0 + ixm)) * sx + 1.0f;
    float X01 = (__ldg(d0 + iyp) - __ldg(d0 + iym)) * sy;
    float X02 = (__ldg(d0 + izp) - __ldg(d0 + izm)) * sz;
    float X10 = (__ldg(d1 + ixp) - __ldg(d1 + ixm)) * sx;
    float X11 = (__ldg(d1 + iyp) - __ldg(d1 + iym)) * sy + 1.0f;
    float X12 = (__ldg(d1 + izp) - __ldg(d1 + izm)) * sz;
    float X20 = (__ldg(d2 + ixp) - __ldg(d2 + ixm)) * sx;
    float X21 = (__ldg(d2 + iyp) - __ldg(d2 + iym)) * sy;
    float X22 = (__ldg(d2 + izp) - __ldg(d2 + izm)) * sz + 1.0f;

    // ---- Trilinear warp, border clamp ----
    float cx = fminf(fmaxf((float)x + u0, 0.0f), (float)(H - 1));
    float cy = fminf(fmaxf((float)y + u1, 0.0f), (float)(W - 1));
    float cz = fminf(fmaxf((float)z + u2, 0.0f), (float)(Dz - 1));
    float x0f = floorf(cx), y0f = floorf(cy), z0f = floorf(cz);
    int x0 = (int)x0f, y0 = (int)y0f, z0 = (int)z0f;
    int x1 = min(x0 + 1, H - 1), y1 = min(y0 + 1, W - 1), z1 = min(z0 + 1, Dz - 1);
    float fx = cx - x0f, fy = cy - y0f, fz = cz - z0f;

    int r00 = (x0 * W + y0) * Dz, r01 = (x0 * W + y1) * Dz;
    int r10 = (x1 * W + y0) * Dz, r11 = (x1 * W + y1) * Dz;

    float m[6];
#pragma unroll
    for (int c = 0; c < 6; ++c) {
        const float* __restrict__ p = dti + c * HWD;
        float v000 = __ldg(p + r00 + z0), v001 = __ldg(p + r00 + z1);
        float v010 = __ldg(p + r01 + z0), v011 = __ldg(p + r01 + z1);
        float v100 = __ldg(p + r10 + z0), v101 = __ldg(p + r10 + z1);
        float v110 = __ldg(p + r11 + z0), v111 = __ldg(p + r11 + z1);
        float c00 = v000 + (v001 - v000) * fz;
        float c01 = v010 + (v011 - v010) * fz;
        float c10 = v100 + (v101 - v100) * fz;
        float c11 = v110 + (v111 - v110) * fz;
        float c0 = c00 + (c01 - c00) * fy;
        float c1 = c10 + (c11 - c10) * fy;
        m[c] = c0 + (c1 - c0) * fx;
    }

    // ---- Polar factor of J: determinant-scaled Newton, X -> 0.5(gX + cof(X)/(g det)) ----
#pragma unroll
    for (int it = 0; it < 10; ++it) {
        float C00 = X11 * X22 - X12 * X21;
        float C01 = X12 * X20 - X10 * X22;
        float C02 = X10 * X21 - X11 * X20;
        float C10 = X02 * X21 - X01 * X22;
        float C11 = X00 * X22 - X02 * X20;
        float C12 = X01 * X20 - X00 * X21;
        float C20 = X01 * X12 - X02 * X11;
        float C21 = X02 * X10 - X00 * X12;
        float C22 = X00 * X11 - X01 * X10;
        float det = X00 * C00 + X01 * C01 + X02 * C02;
        float ad  = fabsf(det) + 1e-30f;
        float g   = rcbrtf(ad);                       // |det|^(-1/3)
        float s   = 0.5f / (g * copysignf(ad, det));  // 0.5 / (g*det), safe
        float h   = 0.5f * g;
        X00 = h * X00 + s * C00; X01 = h * X01 + s * C01; X02 = h * X02 + s * C02;
        X10 = h * X10 + s * C10; X11 = h * X11 + s * C11; X12 = h * X12 + s * C12;
        X20 = h * X20 + s * C20; X21 = h * X21 + s * C21; X22 = h * X22 + s * C22;
    }
    // X is now R = U Vh (orthogonal polar factor, det sign preserved)

    // ---- Dp = R^T M R, M symmetric from lotri channels [0,1,3;1,2,4;3,4,5] ----
    float M00 = m[0], M01 = m[1], M02 = m[3];
    float M11 = m[2], M12 = m[4], M22 = m[5];

    // T = M * R
    float T00 = M00 * X00 + M01 * X10 + M02 * X20;
    float T01 = M00 * X01 + M01 * X11 + M02 * X21;
    float T02 = M00 * X02 + M01 * X12 + M02 * X22;
    float T10 = M01 * X00 + M11 * X10 + M12 * X20;
    float T11 = M01 * X01 + M11 * X11 + M12 * X21;
    float T12 = M01 * X02 + M11 * X12 + M12 * X22;
    float T20 = M02 * X00 + M12 * X10 + M22 * X20;
    float T21 = M02 * X01 + M12 * X11 + M22 * X21;
    float T22 = M02 * X02 + M12 * X12 + M22 * X22;

    // Dp[i][j] = sum_k R[k][i] * T[k][j]
    float P00 = X00 * T00 + X10 * T10 + X20 * T20;
    float P10 = X01 * T00 + X11 * T10 + X21 * T20;
    float P11 = X01 * T01 + X11 * T11 + X21 * T21;
    float P20 = X02 * T00 + X12 * T10 + X22 * T20;
    float P21 = X02 * T01 + X12 * T11 + X22 * T21;
    float P22 = X02 * T02 + X12 * T12 + X22 * T22;

    out[idx]            = P00;
    out[HWD + idx]      = P10;
    out[2 * HWD + idx]  = P11;
    out[3 * HWD + idx]  = P20;
    out[4 * HWD + idx]  = P21;
    out[5 * HWD + idx]  = P22;
}

extern "C" void kernel_launch(void* const* d_in, const int* in_sizes, int n_in,
                              void* d_out, int out_size)
{
    const float* a = (const float*)d_in[0];
    const float* b = (const float*)d_in[1];
    const float* dti = a;
    const float* ddf = b;
    if (n_in >= 2 && in_sizes[0] == 3 * HWD) { dti = b; ddf = a; }  // defensive order sniff
    float* out = (float*)d_out;

    warp_dti_kernel<<<HWD / 256, 256>>>(dti, ddf, out);
}

// round 2
// speedup vs baseline: 1.1744x; 1.1744x over previous
#include <cuda_runtime.h>

static constexpr int H = 128, W = 128, Dz = 128;
static constexpr int HWD = H * W * Dz;

__global__ __launch_bounds__(256)
void warp_dti_kernel(const float* __restrict__ dti,
                     const float* __restrict__ ddf,
                     float* __restrict__ out)
{
    int idx = blockIdx.x * 256 + threadIdx.x;
    if (idx >= HWD) return;
    int z = idx & (Dz - 1);
    int y = (idx >> 7) & (W - 1);
    int x = idx >> 14;

    const float* __restrict__ d0 = ddf;
    const float* __restrict__ d1 = ddf + HWD;
    const float* __restrict__ d2 = ddf + 2 * HWD;

    float u0 = __ldg(d0 + idx), u1 = __ldg(d1 + idx), u2 = __ldg(d2 + idx);

    // ---- Jacobian via jnp.gradient semantics (central interior, one-sided edges) ----
    int xp = min(x + 1, H - 1), xm = max(x - 1, 0);
    int yp = min(y + 1, W - 1), ym = max(y - 1, 0);
    int zp = min(z + 1, Dz - 1), zm = max(z - 1, 0);
    float sx = 1.0f / (float)(xp - xm);
    float sy = 1.0f / (float)(yp - ym);
    float sz = 1.0f / (float)(zp - zm);

    int byz = y * Dz + z;
    int ixp = xp * (W * Dz) + byz, ixm = xm * (W * Dz) + byz;
    int row = x * (W * Dz);
    int iyp = row + yp * Dz + z, iym = row + ym * Dz + z;
    int izp = idx + (zp - z), izm = idx - (z - zm);

    // J[i][j] = d ddf_i / d axis_j + delta_ij
    float X00 = (__ldg(d0 + ixp) - __ldg(d0 + ixm)) * sx + 1.0f;
    float X01 = (__ldg(d0 + iyp) - __ldg(d0 + iym)) * sy;
    float X02 = (__ldg(d0 + izp) - __ldg(d0 + izm)) * sz;
    float X10 = (__ldg(d1 + ixp) - __ldg(d1 + ixm)) * sx;
    float X11 = (__ldg(d1 + iyp) - __ldg(d1 + iym)) * sy + 1.0f;
    float X12 = (__ldg(d1 + izp) - __ldg(d1 + izm)) * sz;
    float X20 = (__ldg(d2 + ixp) - __ldg(d2 + ixm)) * sx;
    float X21 = (__ldg(d2 + iyp) - __ldg(d2 + iym)) * sy;
    float X22 = (__ldg(d2 + izp) - __ldg(d2 + izm)) * sz + 1.0f;

    // ---- Trilinear warp, border clamp ----
    float cx = fminf(fmaxf((float)x + u0, 0.0f), (float)(H - 1));
    float cy = fminf(fmaxf((float)y + u1, 0.0f), (float)(W - 1));
    float cz = fminf(fmaxf((float)z + u2, 0.0f), (float)(Dz - 1));
    float x0f = floorf(cx), y0f = floorf(cy), z0f = floorf(cz);
    int x0 = (int)x0f, y0 = (int)y0f, z0 = (int)z0f;
    int x1 = min(x0 + 1, H - 1), y1 = min(y0 + 1, W - 1), z1 = min(z0 + 1, Dz - 1);
    float fx = cx - x0f, fy = cy - y0f, fz = cz - z0f;

    int r00 = (x0 * W + y0) * Dz, r01 = (x0 * W + y1) * Dz;
    int r10 = (x1 * W + y0) * Dz, r11 = (x1 * W + y1) * Dz;

    float m[6];
#pragma unroll
    for (int c = 0; c < 6; ++c) {
        const float* __restrict__ p = dti + c * HWD;
        float v000 = __ldg(p + r00 + z0), v001 = __ldg(p + r00 + z1);
        float v010 = __ldg(p + r01 + z0), v011 = __ldg(p + r01 + z1);
        float v100 = __ldg(p + r10 + z0), v101 = __ldg(p + r10 + z1);
        float v110 = __ldg(p + r11 + z0), v111 = __ldg(p + r11 + z1);
        float c00 = v000 + (v001 - v000) * fz;
        float c01 = v010 + (v011 - v010) * fz;
        float c10 = v100 + (v101 - v100) * fz;
        float c11 = v110 + (v111 - v110) * fz;
        float c0 = c00 + (c01 - c00) * fy;
        float c1 = c10 + (c11 - c10) * fy;
        m[c] = c0 + (c1 - c0) * fx;
    }

    // ---- Polar factor of J: determinant-scaled Newton ----
    // X <- 0.5*(g*X + cof(X)/(g*det)),  g = |det|^(-1/3)
    // Key identity: 1/(g*det) = sign(det)*|det|^(-2/3) = sign(det)*g*g  -> NO division.
#pragma unroll
    for (int it = 0; it < 7; ++it) {
        float C00 = X11 * X22 - X12 * X21;
        float C01 = X12 * X20 - X10 * X22;
        float C02 = X10 * X21 - X11 * X20;
        float C10 = X02 * X21 - X01 * X22;
        float C11 = X00 * X22 - X02 * X20;
        float C12 = X01 * X20 - X00 * X21;
        float C20 = X01 * X12 - X02 * X11;
        float C21 = X02 * X10 - X00 * X12;
        float C22 = X00 * X11 - X01 * X10;
        float det = X00 * C00 + X01 * C01 + X02 * C02;
        float ad  = fabsf(det) + 1e-30f;
        float g   = rcbrtf(ad);                        // |det|^(-1/3)
        float s   = 0.5f * copysignf(g * g, det);      // 0.5/(g*det), division-free
        float h   = 0.5f * g;
        X00 = h * X00 + s * C00; X01 = h * X01 + s * C01; X02 = h * X02 + s * C02;
        X10 = h * X10 + s * C10; X11 = h * X11 + s * C11; X12 = h * X12 + s * C12;
        X20 = h * X20 + s * C20; X21 = h * X21 + s * C21; X22 = h * X22 + s * C22;
    }
    // X is now R = U Vh (orthogonal polar factor, det sign preserved)

    // ---- Dp = R^T M R, M symmetric from lotri channels [0,1,3;1,2,4;3,4,5] ----
    float M00 = m[0], M01 = m[1], M02 = m[3];
    float M11 = m[2], M12 = m[4], M22 = m[5];

    // T = M * R
    float T00 = M00 * X00 + M01 * X10 + M02 * X20;
    float T01 = M00 * X01 + M01 * X11 + M02 * X21;
    float T02 = M00 * X02 + M01 * X12 + M02 * X22;
    float T10 = M01 * X00 + M11 * X10 + M12 * X20;
    float T11 = M01 * X01 + M11 * X11 + M12 * X21;
    float T12 = M01 * X02 + M11 * X12 + M12 * X22;
    float T20 = M02 * X00 + M12 * X10 + M22 * X20;
    float T21 = M02 * X01 + M12 * X11 + M22 * X21;
    float T22 = M02 * X02 + M12 * X12 + M22 * X22;

    // Dp[i][j] = sum_k R[k][i] * T[k][j]
    float P00 = X00 * T00 + X10 * T10 + X20 * T20;
    float P10 = X01 * T00 + X11 * T10 + X21 * T20;
    float P11 = X01 * T01 + X11 * T11 + X21 * T21;
    float P20 = X02 * T00 + X12 * T10 + X22 * T20;
    float P21 = X02 * T01 + X12 * T11 + X22 * T21;
    float P22 = X02 * T02 + X12 * T12 + X22 * T22;

    out[idx]            = P00;
    out[HWD + idx]      = P10;
    out[2 * HWD + idx]  = P11;
    out[3 * HWD + idx]  = P20;
    out[4 * HWD + idx]  = P21;
    out[5 * HWD + idx]  = P22;
}

extern "C" void kernel_launch(void* const* d_in, const int* in_sizes, int n_in,
                              void* d_out, int out_size)
{
    const float* a = (const float*)d_in[0];
    const float* b = (const float*)d_in[1];
    const float* dti = a;
    const float* ddf = b;
    if (n_in >= 2 && in_sizes[0] == 3 * HWD) { dti = b; ddf = a; }  // defensive order sniff
    float* out = (float*)d_out;

    warp_dti_kernel<<<HWD / 256, 256>>>(dti, ddf, out);
}